// round 1
// baseline (speedup 1.0000x reference)
#include <cuda_runtime.h>

#define BATCH 16
#define HW 3136
#define W56 56
#define CIN 256
#define CMID 64

// ---------------- scratch (device globals; no allocation) ----------------
__device__ __align__(16) float g_out1[BATCH * CMID * HW];   // after conv1+bn1+relu
__device__ __align__(16) float g_wbuf[BATCH * 196 * HW];    // involution dynamic weights
__device__ __align__(16) float g_out2[BATCH * CMID * HW];   // after involution+bn2+relu

// ---------------- packed f32x2 helpers ----------------
__device__ __forceinline__ unsigned long long pk2(float lo, float hi) {
    unsigned long long r;
    asm("mov.b64 %0, {%1, %2};" : "=l"(r) : "f"(lo), "f"(hi));
    return r;
}
__device__ __forceinline__ unsigned long long fma2(unsigned long long a,
                                                   unsigned long long b,
                                                   unsigned long long c) {
    unsigned long long d;
    asm("fma.rn.f32x2 %0, %1, %2, %3;" : "=l"(d) : "l"(a), "l"(b), "l"(c));
    return d;
}
__device__ __forceinline__ float2 up2(unsigned long long v) {
    float2 f;
    asm("mov.b64 {%0, %1}, %2;" : "=f"(f.x), "=f"(f.y) : "l"(v));
    return f;
}

// =====================================================================
// Kernel 1: conv1 (1x1, 256->64) + BN1 + ReLU  ->  g_out1
// block: 224 thr; tile: 112 px x 64 oc. thread: 4 px x 8 oc.
// =====================================================================
__global__ __launch_bounds__(224) void conv1_kernel(
    const float* __restrict__ x, const float* __restrict__ w,
    const float* __restrict__ bg, const float* __restrict__ bb,
    const float* __restrict__ bm, const float* __restrict__ bv)
{
    __shared__ __align__(16) float xs[64 * 112];
    __shared__ float ws[64 * 64];
    const int b   = blockIdx.y;
    const int hw0 = blockIdx.x * 112;
    const int t   = threadIdx.x;
    const int pg  = t % 28;
    const int og  = t / 28;
    const float* xb = x + (size_t)b * CIN * HW + hw0;

    unsigned long long acc[8][2];
#pragma unroll
    for (int j = 0; j < 8; j++) { acc[j][0] = 0ull; acc[j][1] = 0ull; }

    for (int c0 = 0; c0 < CIN; c0 += 64) {
        __syncthreads();
        for (int i = t; i < 64 * 112; i += 224)
            xs[i] = xb[(size_t)(c0 + i / 112) * HW + (i % 112)];
        for (int i = t; i < 64 * 64; i += 224)
            ws[i] = w[(i >> 6) * CIN + c0 + (i & 63)];
        __syncthreads();
#pragma unroll 4
        for (int c = 0; c < 64; ++c) {
            ulonglong2 xv = *reinterpret_cast<const ulonglong2*>(&xs[c * 112 + pg * 4]);
#pragma unroll
            for (int j = 0; j < 8; ++j) {
                float wv = ws[(og * 8 + j) * 64 + c];
                unsigned long long wp = pk2(wv, wv);
                acc[j][0] = fma2(wp, xv.x, acc[j][0]);
                acc[j][1] = fma2(wp, xv.y, acc[j][1]);
            }
        }
    }
    float* ob = g_out1 + (size_t)b * CMID * HW + hw0 + pg * 4;
#pragma unroll
    for (int j = 0; j < 8; ++j) {
        int oc = og * 8 + j;
        float sc = bg[oc] * rsqrtf(bv[oc] + 1e-5f);
        float sh = bb[oc] - bm[oc] * sc;
        float2 a0 = up2(acc[j][0]);
        float2 a1 = up2(acc[j][1]);
        float4 o;
        o.x = fmaxf(a0.x * sc + sh, 0.f);
        o.y = fmaxf(a0.y * sc + sh, 0.f);
        o.z = fmaxf(a1.x * sc + sh, 0.f);
        o.w = fmaxf(a1.y * sc + sh, 0.f);
        *reinterpret_cast<float4*>(&ob[(size_t)oc * HW]) = o;
    }
}

// =====================================================================
// Kernel 2: weight branch: (64->16 1x1)+BN+ReLU, (16->196 1x1)+bias -> g_wbuf
// block: 256 thr, 2 px/thread (512 px/block), f32x2-packed over pixel pairs.
// =====================================================================
__global__ __launch_bounds__(256) void wbranch_kernel(
    const float* __restrict__ w1,
    const float* __restrict__ bg, const float* __restrict__ bb,
    const float* __restrict__ bm, const float* __restrict__ bv,
    const float* __restrict__ w2, const float* __restrict__ bias)
{
    __shared__ float w1s[16 * 64];
    __shared__ float w2s[196 * 16];
    __shared__ float biass[196];
    __shared__ float sc2[16], sh2[16];
    const int t = threadIdx.x;
    for (int i = t; i < 1024; i += 256) w1s[i] = w1[i];
    for (int i = t; i < 3136; i += 256) w2s[i] = w2[i];
    if (t < 196) biass[t] = bias[t];
    if (t < 16) {
        float s = bg[t] * rsqrtf(bv[t] + 1e-5f);
        sc2[t] = s; sh2[t] = bb[t] - bm[t] * s;
    }
    __syncthreads();

    const int b = blockIdx.y;
    const int p = blockIdx.x * 512 + t * 2;
    if (p >= HW) return;

    const float* in = g_out1 + (size_t)b * CMID * HW + p;
    unsigned long long mid[16];
#pragma unroll
    for (int m = 0; m < 16; m++) mid[m] = 0ull;
    for (int c = 0; c < 64; ++c) {
        float2 xv = *reinterpret_cast<const float2*>(&in[(size_t)c * HW]);
        unsigned long long xp = pk2(xv.x, xv.y);
#pragma unroll
        for (int m = 0; m < 16; ++m) {
            float wv = w1s[m * 64 + c];
            mid[m] = fma2(pk2(wv, wv), xp, mid[m]);
        }
    }
#pragma unroll
    for (int m = 0; m < 16; ++m) {
        float2 v = up2(mid[m]);
        v.x = fmaxf(v.x * sc2[m] + sh2[m], 0.f);
        v.y = fmaxf(v.y * sc2[m] + sh2[m], 0.f);
        mid[m] = pk2(v.x, v.y);
    }
    float* ob = g_wbuf + (size_t)b * 196 * HW + p;
    for (int o = 0; o < 196; ++o) {
        unsigned long long a = pk2(biass[o], biass[o]);
#pragma unroll
        for (int m = 0; m < 16; ++m) {
            float wv = w2s[o * 16 + m];
            a = fma2(pk2(wv, wv), mid[m], a);
        }
        float2 r = up2(a);
        *reinterpret_cast<float2*>(&ob[(size_t)o * HW]) = r;
    }
}

// =====================================================================
// Kernel 3: involution (K=7, G=4, GC=16) + BN2 + ReLU -> g_out2
// grid (2,7, B*G); block 224 = 28x8 spatial tile; smem halo [16][14][34]
// =====================================================================
__global__ __launch_bounds__(224) void invol_kernel(
    const float* __restrict__ bg, const float* __restrict__ bb,
    const float* __restrict__ bm, const float* __restrict__ bv)
{
    __shared__ float sm[16 * 476];   // [c][14][34]
    __shared__ float sc2[16], sh2[16];
    const int t  = threadIdx.x;
    const int bz = blockIdx.z;
    const int b  = bz >> 2, g = bz & 3;
    const int x0 = blockIdx.x * 28, y0 = blockIdx.y * 8;
    const float* in = g_out1 + ((size_t)b * CMID + g * 16) * HW;

    if (t < 16) {
        int gc = g * 16 + t;
        float s = bg[gc] * rsqrtf(bv[gc] + 1e-5f);
        sc2[t] = s; sh2[t] = bb[gc] - bm[gc] * s;
    }
    for (int i = t; i < 16 * 476; i += 224) {
        int c = i / 476, r = i % 476;
        int iy = r / 34, ix = r % 34;
        int gy = y0 + iy - 3, gx = x0 + ix - 3;
        sm[i] = (gy >= 0 && gy < W56 && gx >= 0 && gx < W56)
                    ? in[(size_t)c * HW + gy * W56 + gx] : 0.f;
    }
    __syncthreads();

    const int lx = t % 28, ly = t / 28;
    const int pix = (y0 + ly) * W56 + x0 + lx;
    const float* wb = g_wbuf + ((size_t)b * 196 + g * 49) * HW + pix;

    float acc[16];
#pragma unroll
    for (int c = 0; c < 16; ++c) acc[c] = 0.f;

    for (int kh = 0; kh < 7; ++kh) {
#pragma unroll
        for (int kw = 0; kw < 7; ++kw) {
            float wk = wb[(size_t)(kh * 7 + kw) * HW];
            const float* sp = &sm[(ly + kh) * 34 + lx + kw];
#pragma unroll
            for (int c = 0; c < 16; ++c)
                acc[c] += wk * sp[c * 476];
        }
    }
    float* ob = g_out2 + ((size_t)b * CMID + g * 16) * HW + pix;
#pragma unroll
    for (int c = 0; c < 16; ++c)
        ob[(size_t)c * HW] = fmaxf(acc[c] * sc2[c] + sh2[c], 0.f);
}

// =====================================================================
// Kernel 4: conv3 (1x1, 64->256) + BN3 + identity add + ReLU -> d_out
// grid (28, 4 oc-chunks, B); block 224; tile 112 px x 64 oc.
// =====================================================================
__global__ __launch_bounds__(224) void conv3_kernel(
    const float* __restrict__ x, const float* __restrict__ w,
    const float* __restrict__ bg, const float* __restrict__ bb,
    const float* __restrict__ bm, const float* __restrict__ bv,
    float* __restrict__ out)
{
    __shared__ __align__(16) float xs[64 * 112];
    __shared__ float ws[64 * 64];
    const int b   = blockIdx.z;
    const int oc0 = blockIdx.y * 64;
    const int hw0 = blockIdx.x * 112;
    const int t   = threadIdx.x;
    const int pg  = t % 28;
    const int og  = t / 28;

    const float* xb = g_out2 + (size_t)b * CMID * HW + hw0;
    for (int i = t; i < 64 * 112; i += 224)
        xs[i] = xb[(size_t)(i / 112) * HW + (i % 112)];
    for (int i = t; i < 64 * 64; i += 224)
        ws[i] = w[(size_t)(oc0 + (i >> 6)) * 64 + (i & 63)];
    __syncthreads();

    unsigned long long acc[8][2];
#pragma unroll
    for (int j = 0; j < 8; j++) { acc[j][0] = 0ull; acc[j][1] = 0ull; }

#pragma unroll 4
    for (int c = 0; c < 64; ++c) {
        ulonglong2 xv = *reinterpret_cast<const ulonglong2*>(&xs[c * 112 + pg * 4]);
#pragma unroll
        for (int j = 0; j < 8; ++j) {
            float wv = ws[(og * 8 + j) * 64 + c];
            unsigned long long wp = pk2(wv, wv);
            acc[j][0] = fma2(wp, xv.x, acc[j][0]);
            acc[j][1] = fma2(wp, xv.y, acc[j][1]);
        }
    }

    const float* idb = x   + (size_t)b * CIN * HW + hw0 + pg * 4;
    float*       ob  = out + (size_t)b * CIN * HW + hw0 + pg * 4;
#pragma unroll
    for (int j = 0; j < 8; ++j) {
        int oc = oc0 + og * 8 + j;
        float sc = bg[oc] * rsqrtf(bv[oc] + 1e-5f);
        float sh = bb[oc] - bm[oc] * sc;
        float2 a0 = up2(acc[j][0]);
        float2 a1 = up2(acc[j][1]);
        float4 idv = *reinterpret_cast<const float4*>(&idb[(size_t)oc * HW]);
        float4 o;
        o.x = fmaxf(a0.x * sc + sh + idv.x, 0.f);
        o.y = fmaxf(a0.y * sc + sh + idv.y, 0.f);
        o.z = fmaxf(a1.x * sc + sh + idv.z, 0.f);
        o.w = fmaxf(a1.y * sc + sh + idv.w, 0.f);
        *reinterpret_cast<float4*>(&ob[(size_t)oc * HW]) = o;
    }
}

// =====================================================================
extern "C" void kernel_launch(void* const* d_in, const int* in_sizes, int n_in,
                              void* d_out, int out_size) {
    const float* x        = (const float*)d_in[0];
    const float* conv1_w  = (const float*)d_in[1];
    const float* bn1_g    = (const float*)d_in[2];
    const float* bn1_b    = (const float*)d_in[3];
    const float* bn1_m    = (const float*)d_in[4];
    const float* bn1_v    = (const float*)d_in[5];
    const float* inv_c1_w = (const float*)d_in[6];
    const float* inv_bn_g = (const float*)d_in[7];
    const float* inv_bn_b = (const float*)d_in[8];
    const float* inv_bn_m = (const float*)d_in[9];
    const float* inv_bn_v = (const float*)d_in[10];
    const float* inv_c2_w = (const float*)d_in[11];
    const float* inv_c2_b = (const float*)d_in[12];
    const float* bn2_g    = (const float*)d_in[13];
    const float* bn2_b    = (const float*)d_in[14];
    const float* bn2_m    = (const float*)d_in[15];
    const float* bn2_v    = (const float*)d_in[16];
    const float* conv3_w  = (const float*)d_in[17];
    const float* bn3_g    = (const float*)d_in[18];
    const float* bn3_b    = (const float*)d_in[19];
    const float* bn3_m    = (const float*)d_in[20];
    const float* bn3_v    = (const float*)d_in[21];
    float* out = (float*)d_out;

    dim3 g1(28, BATCH);
    conv1_kernel<<<g1, 224>>>(x, conv1_w, bn1_g, bn1_b, bn1_m, bn1_v);

    dim3 g2(7, BATCH);
    wbranch_kernel<<<g2, 256>>>(inv_c1_w, inv_bn_g, inv_bn_b, inv_bn_m, inv_bn_v,
                                inv_c2_w, inv_c2_b);

    dim3 g3(2, 7, BATCH * 4);
    invol_kernel<<<g3, 224>>>(bn2_g, bn2_b, bn2_m, bn2_v);

    dim3 g4(28, 4, BATCH);
    conv3_kernel<<<g4, 224>>>(x, conv3_w, bn3_g, bn3_b, bn3_m, bn3_v, out);
}

// round 2
// speedup vs baseline: 1.1682x; 1.1682x over previous
#include <cuda_runtime.h>

#define BATCH 16
#define HW 3136
#define W56 56
#define CIN 256
#define CMID 64

// ---------------- scratch (device globals; no allocation) ----------------
__device__ __align__(16) float g_out1[BATCH * CMID * HW];   // after conv1+bn1+relu
__device__ __align__(16) float g_wbuf[BATCH * 196 * HW];    // involution dynamic weights
__device__ __align__(16) float g_out2[BATCH * CMID * HW];   // after involution+bn2+relu

// ---------------- packed f32x2 helpers ----------------
__device__ __forceinline__ unsigned long long pk2(float lo, float hi) {
    unsigned long long r;
    asm("mov.b64 %0, {%1, %2};" : "=l"(r) : "f"(lo), "f"(hi));
    return r;
}
__device__ __forceinline__ unsigned long long fma2(unsigned long long a,
                                                   unsigned long long b,
                                                   unsigned long long c) {
    unsigned long long d;
    asm("fma.rn.f32x2 %0, %1, %2, %3;" : "=l"(d) : "l"(a), "l"(b), "l"(c));
    return d;
}
__device__ __forceinline__ float2 up2(unsigned long long v) {
    float2 f;
    asm("mov.b64 {%0, %1}, %2;" : "=f"(f.x), "=f"(f.y) : "l"(v));
    return f;
}

// =====================================================================
// Kernel 1: conv1 (1x1, 256->64) + BN1 + ReLU  ->  g_out1
// block: 224 thr; tile: 112 px x 64 oc. thread: 4 px x 8 oc.
// inner loop: c in blocks of 4, float4 weight loads (LDS.128 only).
// =====================================================================
__global__ __launch_bounds__(224, 4) void conv1_kernel(
    const float* __restrict__ x, const float* __restrict__ w,
    const float* __restrict__ bg, const float* __restrict__ bb,
    const float* __restrict__ bm, const float* __restrict__ bv)
{
    __shared__ __align__(16) float xs[64 * 112];
    __shared__ __align__(16) float ws[64 * 64];
    const int b   = blockIdx.y;
    const int hw0 = blockIdx.x * 112;
    const int t   = threadIdx.x;
    const int pg  = t % 28;
    const int og  = t / 28;
    const float* xb = x + (size_t)b * CIN * HW + hw0;

    unsigned long long acc[8][2];
#pragma unroll
    for (int j = 0; j < 8; j++) { acc[j][0] = 0ull; acc[j][1] = 0ull; }

    for (int c0 = 0; c0 < CIN; c0 += 64) {
        __syncthreads();
        for (int i = t; i < 64 * 112; i += 224)
            xs[i] = xb[(size_t)(c0 + i / 112) * HW + (i % 112)];
        for (int i = t; i < 64 * 64; i += 224)
            ws[i] = w[(i >> 6) * CIN + c0 + (i & 63)];
        __syncthreads();
#pragma unroll 2
        for (int c4 = 0; c4 < 64; c4 += 4) {
            ulonglong2 xv0 = *reinterpret_cast<const ulonglong2*>(&xs[(c4 + 0) * 112 + pg * 4]);
            ulonglong2 xv1 = *reinterpret_cast<const ulonglong2*>(&xs[(c4 + 1) * 112 + pg * 4]);
            ulonglong2 xv2 = *reinterpret_cast<const ulonglong2*>(&xs[(c4 + 2) * 112 + pg * 4]);
            ulonglong2 xv3 = *reinterpret_cast<const ulonglong2*>(&xs[(c4 + 3) * 112 + pg * 4]);
#pragma unroll
            for (int j = 0; j < 8; ++j) {
                float4 wv = *reinterpret_cast<const float4*>(&ws[(og * 8 + j) * 64 + c4]);
                unsigned long long w0 = pk2(wv.x, wv.x);
                unsigned long long w1 = pk2(wv.y, wv.y);
                unsigned long long w2 = pk2(wv.z, wv.z);
                unsigned long long w3 = pk2(wv.w, wv.w);
                acc[j][0] = fma2(w0, xv0.x, acc[j][0]);
                acc[j][1] = fma2(w0, xv0.y, acc[j][1]);
                acc[j][0] = fma2(w1, xv1.x, acc[j][0]);
                acc[j][1] = fma2(w1, xv1.y, acc[j][1]);
                acc[j][0] = fma2(w2, xv2.x, acc[j][0]);
                acc[j][1] = fma2(w2, xv2.y, acc[j][1]);
                acc[j][0] = fma2(w3, xv3.x, acc[j][0]);
                acc[j][1] = fma2(w3, xv3.y, acc[j][1]);
            }
        }
    }
    float* ob = g_out1 + (size_t)b * CMID * HW + hw0 + pg * 4;
#pragma unroll
    for (int j = 0; j < 8; ++j) {
        int oc = og * 8 + j;
        float sc = bg[oc] * rsqrtf(bv[oc] + 1e-5f);
        float sh = bb[oc] - bm[oc] * sc;
        float2 a0 = up2(acc[j][0]);
        float2 a1 = up2(acc[j][1]);
        float4 o;
        o.x = fmaxf(a0.x * sc + sh, 0.f);
        o.y = fmaxf(a0.y * sc + sh, 0.f);
        o.z = fmaxf(a1.x * sc + sh, 0.f);
        o.w = fmaxf(a1.y * sc + sh, 0.f);
        *reinterpret_cast<float4*>(&ob[(size_t)oc * HW]) = o;
    }
}

// =====================================================================
// Kernel 2: weight branch: (64->16 1x1)+BN+ReLU, (16->196 1x1)+bias -> g_wbuf
// block: 128 thr, 2 px/thread (256 px/block), 208 blocks.
// =====================================================================
__global__ __launch_bounds__(128) void wbranch_kernel(
    const float* __restrict__ w1,
    const float* __restrict__ bg, const float* __restrict__ bb,
    const float* __restrict__ bm, const float* __restrict__ bv,
    const float* __restrict__ w2, const float* __restrict__ bias)
{
    __shared__ __align__(16) float w1s[16 * 64];
    __shared__ __align__(16) float w2s[196 * 16];
    __shared__ float biass[196];
    __shared__ float sc2[16], sh2[16];
    const int t = threadIdx.x;
    for (int i = t; i < 1024; i += 128) w1s[i] = w1[i];
    for (int i = t; i < 3136; i += 128) w2s[i] = w2[i];
    for (int i = t; i < 196; i += 128) biass[i] = bias[i];
    if (t < 16) {
        float s = bg[t] * rsqrtf(bv[t] + 1e-5f);
        sc2[t] = s; sh2[t] = bb[t] - bm[t] * s;
    }
    __syncthreads();

    const int b = blockIdx.y;
    const int p = blockIdx.x * 256 + t * 2;
    if (p >= HW) return;

    const float* in = g_out1 + (size_t)b * CMID * HW + p;
    unsigned long long mid[16];
#pragma unroll
    for (int m = 0; m < 16; m++) mid[m] = 0ull;
#pragma unroll 2
    for (int c4 = 0; c4 < 64; c4 += 4) {
        unsigned long long xp[4];
#pragma unroll
        for (int q = 0; q < 4; ++q) {
            float2 xv = *reinterpret_cast<const float2*>(&in[(size_t)(c4 + q) * HW]);
            xp[q] = pk2(xv.x, xv.y);
        }
#pragma unroll
        for (int m = 0; m < 16; ++m) {
            float4 wv = *reinterpret_cast<const float4*>(&w1s[m * 64 + c4]);
            mid[m] = fma2(pk2(wv.x, wv.x), xp[0], mid[m]);
            mid[m] = fma2(pk2(wv.y, wv.y), xp[1], mid[m]);
            mid[m] = fma2(pk2(wv.z, wv.z), xp[2], mid[m]);
            mid[m] = fma2(pk2(wv.w, wv.w), xp[3], mid[m]);
        }
    }
#pragma unroll
    for (int m = 0; m < 16; ++m) {
        float2 v = up2(mid[m]);
        v.x = fmaxf(v.x * sc2[m] + sh2[m], 0.f);
        v.y = fmaxf(v.y * sc2[m] + sh2[m], 0.f);
        mid[m] = pk2(v.x, v.y);
    }
    float* ob = g_wbuf + (size_t)b * 196 * HW + p;
#pragma unroll 2
    for (int o = 0; o < 196; ++o) {
        float4 a0 = *reinterpret_cast<const float4*>(&w2s[o * 16 + 0]);
        float4 a1 = *reinterpret_cast<const float4*>(&w2s[o * 16 + 4]);
        float4 a2 = *reinterpret_cast<const float4*>(&w2s[o * 16 + 8]);
        float4 a3 = *reinterpret_cast<const float4*>(&w2s[o * 16 + 12]);
        unsigned long long a = pk2(biass[o], biass[o]);
        a = fma2(pk2(a0.x, a0.x), mid[0],  a);
        a = fma2(pk2(a0.y, a0.y), mid[1],  a);
        a = fma2(pk2(a0.z, a0.z), mid[2],  a);
        a = fma2(pk2(a0.w, a0.w), mid[3],  a);
        a = fma2(pk2(a1.x, a1.x), mid[4],  a);
        a = fma2(pk2(a1.y, a1.y), mid[5],  a);
        a = fma2(pk2(a1.z, a1.z), mid[6],  a);
        a = fma2(pk2(a1.w, a1.w), mid[7],  a);
        a = fma2(pk2(a2.x, a2.x), mid[8],  a);
        a = fma2(pk2(a2.y, a2.y), mid[9],  a);
        a = fma2(pk2(a2.z, a2.z), mid[10], a);
        a = fma2(pk2(a2.w, a2.w), mid[11], a);
        a = fma2(pk2(a3.x, a3.x), mid[12], a);
        a = fma2(pk2(a3.y, a3.y), mid[13], a);
        a = fma2(pk2(a3.z, a3.z), mid[14], a);
        a = fma2(pk2(a3.w, a3.w), mid[15], a);
        float2 r = up2(a);
        *reinterpret_cast<float2*>(&ob[(size_t)o * HW]) = r;
    }
}

// =====================================================================
// Kernel 3: involution (K=7, G=4, GC=16) + BN2 + ReLU -> g_out2
// grid (2,7, B*G); block 224 = 28x8 tile.
// smem layout [px][c] with stride 20 floats -> conflict-free LDS.128.
// =====================================================================
__global__ __launch_bounds__(224, 4) void invol_kernel(
    const float* __restrict__ bg, const float* __restrict__ bb,
    const float* __restrict__ bm, const float* __restrict__ bv)
{
    __shared__ __align__(16) float sm[476 * 20];   // [14*34 px][16 c], stride 20
    __shared__ float sc2[16], sh2[16];
    const int t  = threadIdx.x;
    const int bz = blockIdx.z;
    const int b  = bz >> 2, g = bz & 3;
    const int x0 = blockIdx.x * 28, y0 = blockIdx.y * 8;
    const float* in = g_out1 + ((size_t)b * CMID + g * 16) * HW;

    if (t < 16) {
        int gc = g * 16 + t;
        float s = bg[gc] * rsqrtf(bv[gc] + 1e-5f);
        sc2[t] = s; sh2[t] = bb[gc] - bm[gc] * s;
    }
    for (int i = t; i < 16 * 476; i += 224) {
        int c = i / 476, r = i % 476;
        int iy = r / 34, ix = r % 34;
        int gy = y0 + iy - 3, gx = x0 + ix - 3;
        sm[r * 20 + c] = (gy >= 0 && gy < W56 && gx >= 0 && gx < W56)
                    ? in[(size_t)c * HW + gy * W56 + gx] : 0.f;
    }
    __syncthreads();

    const int lx = t % 28, ly = t / 28;
    const int pix = (y0 + ly) * W56 + x0 + lx;
    const float* wb = g_wbuf + ((size_t)b * 196 + g * 49) * HW + pix;

    float acc[16];
#pragma unroll
    for (int c = 0; c < 16; ++c) acc[c] = 0.f;

    for (int kh = 0; kh < 7; ++kh) {
#pragma unroll
        for (int kw = 0; kw < 7; ++kw) {
            float wk = wb[(size_t)(kh * 7 + kw) * HW];
            const float4* sp = reinterpret_cast<const float4*>(
                &sm[((ly + kh) * 34 + lx + kw) * 20]);
            float4 v0 = sp[0], v1 = sp[1], v2 = sp[2], v3 = sp[3];
            acc[0]  += wk * v0.x;  acc[1]  += wk * v0.y;
            acc[2]  += wk * v0.z;  acc[3]  += wk * v0.w;
            acc[4]  += wk * v1.x;  acc[5]  += wk * v1.y;
            acc[6]  += wk * v1.z;  acc[7]  += wk * v1.w;
            acc[8]  += wk * v2.x;  acc[9]  += wk * v2.y;
            acc[10] += wk * v2.z;  acc[11] += wk * v2.w;
            acc[12] += wk * v3.x;  acc[13] += wk * v3.y;
            acc[14] += wk * v3.z;  acc[15] += wk * v3.w;
        }
    }
    float* ob = g_out2 + ((size_t)b * CMID + g * 16) * HW + pix;
#pragma unroll
    for (int c = 0; c < 16; ++c)
        ob[(size_t)c * HW] = fmaxf(acc[c] * sc2[c] + sh2[c], 0.f);
}

// =====================================================================
// Kernel 4: conv3 (1x1, 64->256) + BN3 + identity add + ReLU -> d_out
// grid (28, 4 oc-chunks, B); block 224; tile 112 px x 64 oc.
// =====================================================================
__global__ __launch_bounds__(224, 4) void conv3_kernel(
    const float* __restrict__ x, const float* __restrict__ w,
    const float* __restrict__ bg, const float* __restrict__ bb,
    const float* __restrict__ bm, const float* __restrict__ bv,
    float* __restrict__ out)
{
    __shared__ __align__(16) float xs[64 * 112];
    __shared__ __align__(16) float ws[64 * 64];
    const int b   = blockIdx.z;
    const int oc0 = blockIdx.y * 64;
    const int hw0 = blockIdx.x * 112;
    const int t   = threadIdx.x;
    const int pg  = t % 28;
    const int og  = t / 28;

    const float* xb = g_out2 + (size_t)b * CMID * HW + hw0;
    for (int i = t; i < 64 * 112; i += 224)
        xs[i] = xb[(size_t)(i / 112) * HW + (i % 112)];
    for (int i = t; i < 64 * 64; i += 224)
        ws[i] = w[(size_t)(oc0 + (i >> 6)) * 64 + (i & 63)];
    __syncthreads();

    unsigned long long acc[8][2];
#pragma unroll
    for (int j = 0; j < 8; j++) { acc[j][0] = 0ull; acc[j][1] = 0ull; }

#pragma unroll 2
    for (int c4 = 0; c4 < 64; c4 += 4) {
        ulonglong2 xv0 = *reinterpret_cast<const ulonglong2*>(&xs[(c4 + 0) * 112 + pg * 4]);
        ulonglong2 xv1 = *reinterpret_cast<const ulonglong2*>(&xs[(c4 + 1) * 112 + pg * 4]);
        ulonglong2 xv2 = *reinterpret_cast<const ulonglong2*>(&xs[(c4 + 2) * 112 + pg * 4]);
        ulonglong2 xv3 = *reinterpret_cast<const ulonglong2*>(&xs[(c4 + 3) * 112 + pg * 4]);
#pragma unroll
        for (int j = 0; j < 8; ++j) {
            float4 wv = *reinterpret_cast<const float4*>(&ws[(og * 8 + j) * 64 + c4]);
            unsigned long long w0 = pk2(wv.x, wv.x);
            unsigned long long w1 = pk2(wv.y, wv.y);
            unsigned long long w2 = pk2(wv.z, wv.z);
            unsigned long long w3 = pk2(wv.w, wv.w);
            acc[j][0] = fma2(w0, xv0.x, acc[j][0]);
            acc[j][1] = fma2(w0, xv0.y, acc[j][1]);
            acc[j][0] = fma2(w1, xv1.x, acc[j][0]);
            acc[j][1] = fma2(w1, xv1.y, acc[j][1]);
            acc[j][0] = fma2(w2, xv2.x, acc[j][0]);
            acc[j][1] = fma2(w2, xv2.y, acc[j][1]);
            acc[j][0] = fma2(w3, xv3.x, acc[j][0]);
            acc[j][1] = fma2(w3, xv3.y, acc[j][1]);
        }
    }

    const float* idb = x   + (size_t)b * CIN * HW + hw0 + pg * 4;
    float*       ob  = out + (size_t)b * CIN * HW + hw0 + pg * 4;
#pragma unroll
    for (int j = 0; j < 8; ++j) {
        int oc = oc0 + og * 8 + j;
        float sc = bg[oc] * rsqrtf(bv[oc] + 1e-5f);
        float sh = bb[oc] - bm[oc] * sc;
        float2 a0 = up2(acc[j][0]);
        float2 a1 = up2(acc[j][1]);
        float4 idv = *reinterpret_cast<const float4*>(&idb[(size_t)oc * HW]);
        float4 o;
        o.x = fmaxf(a0.x * sc + sh + idv.x, 0.f);
        o.y = fmaxf(a0.y * sc + sh + idv.y, 0.f);
        o.z = fmaxf(a1.x * sc + sh + idv.z, 0.f);
        o.w = fmaxf(a1.y * sc + sh + idv.w, 0.f);
        *reinterpret_cast<float4*>(&ob[(size_t)oc * HW]) = o;
    }
}

// =====================================================================
extern "C" void kernel_launch(void* const* d_in, const int* in_sizes, int n_in,
                              void* d_out, int out_size) {
    const float* x        = (const float*)d_in[0];
    const float* conv1_w  = (const float*)d_in[1];
    const float* bn1_g    = (const float*)d_in[2];
    const float* bn1_b    = (const float*)d_in[3];
    const float* bn1_m    = (const float*)d_in[4];
    const float* bn1_v    = (const float*)d_in[5];
    const float* inv_c1_w = (const float*)d_in[6];
    const float* inv_bn_g = (const float*)d_in[7];
    const float* inv_bn_b = (const float*)d_in[8];
    const float* inv_bn_m = (const float*)d_in[9];
    const float* inv_bn_v = (const float*)d_in[10];
    const float* inv_c2_w = (const float*)d_in[11];
    const float* inv_c2_b = (const float*)d_in[12];
    const float* bn2_g    = (const float*)d_in[13];
    const float* bn2_b    = (const float*)d_in[14];
    const float* bn2_m    = (const float*)d_in[15];
    const float* bn2_v    = (const float*)d_in[16];
    const float* conv3_w  = (const float*)d_in[17];
    const float* bn3_g    = (const float*)d_in[18];
    const float* bn3_b    = (const float*)d_in[19];
    const float* bn3_m    = (const float*)d_in[20];
    const float* bn3_v    = (const float*)d_in[21];
    float* out = (float*)d_out;

    dim3 g1(28, BATCH);
    conv1_kernel<<<g1, 224>>>(x, conv1_w, bn1_g, bn1_b, bn1_m, bn1_v);

    dim3 g2(13, BATCH);
    wbranch_kernel<<<g2, 128>>>(inv_c1_w, inv_bn_g, inv_bn_b, inv_bn_m, inv_bn_v,
                                inv_c2_w, inv_c2_b);

    dim3 g3(2, 7, BATCH * 4);
    invol_kernel<<<g3, 224>>>(bn2_g, bn2_b, bn2_m, bn2_v);

    dim3 g4(28, 4, BATCH);
    conv3_kernel<<<g4, 224>>>(x, conv3_w, bn3_g, bn3_b, bn3_m, bn3_v, out);
}